// round 2
// baseline (speedup 1.0000x reference)
#include <cuda_runtime.h>
#include <cuda_bf16.h>

#define MAXN 50048
#define MAXE 800256
#define NG 128

// ---------------- device scratch (static, no allocation) ----------------
__device__ float g_fs[MAXN * 256];
__device__ float g_fd[MAXN * 256];
__device__ float g_acc[MAXN * 256];
__device__ float g_h[MAXN * 64];
__device__ float g_logit[MAXE * 4];
__device__ int   g_menc[MAXN * 4];
__device__ float g_den[MAXN * 4];
__device__ float g_bnsum[64];
__device__ float g_bnsq[64];
__device__ float g_pooled[NG * 64];
__device__ float g_cat[NG * 192];

// ---------------- helpers ----------------
__device__ __forceinline__ int fenc(float f) {
    int i = __float_as_int(f);
    return (i >= 0) ? i : (i ^ 0x7fffffff);
}
__device__ __forceinline__ float fdec(int i) {
    return __int_as_float((i >= 0) ? i : (i ^ 0x7fffffff));
}
__device__ __forceinline__ float lrelu(float x) { return x > 0.f ? x : 0.2f * x; }

__device__ __forceinline__ void red2(float* p, float a, float b) {
    asm volatile("red.global.add.v2.f32 [%0], {%1,%2};"
                 :: "l"(p), "f"(a), "f"(b) : "memory");
}

// ---------------- per-layer init ----------------
__global__ void init_layer(int N) {
    int idx = blockIdx.x * blockDim.x + threadIdx.x;
    int stride = gridDim.x * blockDim.x;
    for (int i = idx; i < N * 256; i += stride) g_acc[i] = 0.f;
    for (int i = idx; i < N * 4; i += stride) { g_den[i] = 0.f; g_menc[i] = (int)0x80000000; }
    for (int i = idx; i < NG * 64; i += stride) g_pooled[i] = 0.f;
    if (idx < 64) { g_bnsum[idx] = 0.f; g_bnsq[idx] = 0.f; }
}

// ---------------- node GEMM: fs/fd = h @ W + b  (h:[N,64], W:[64,256]) ----------------
// block: 128 rows x 64 cols; grid: (ceil(N/128), 4 col-groups, 2 matrices)
__global__ __launch_bounds__(256) void gemm_kernel(
    const float* __restrict__ feat, int use_feat, int N,
    const float* __restrict__ Ws, const float* __restrict__ bs,
    const float* __restrict__ Wd, const float* __restrict__ bd)
{
    __shared__ float hs[128 * 64];
    __shared__ float ws[64 * 64];
    const float* H = use_feat ? feat : g_h;
    const float* W; const float* B; float* out;
    if (blockIdx.z == 0) { W = Ws; B = bs; out = g_fs; }
    else                 { W = Wd; B = bd; out = g_fd; }
    int cg = blockIdx.y;
    int r0 = blockIdx.x * 128;
    int tid = threadIdx.x;

    for (int idx = tid * 4; idx < 128 * 64; idx += 1024) {
        int r = idx >> 6;
        int gr = r0 + r;
        float4 v = make_float4(0.f, 0.f, 0.f, 0.f);
        if (gr < N) v = *(const float4*)(H + gr * 64 + (idx & 63));
        *(float4*)(hs + idx) = v;
    }
    for (int idx = tid * 4; idx < 64 * 64; idx += 1024) {
        int k = idx >> 6, c = idx & 63;
        *(float4*)(ws + idx) = *(const float4*)(W + k * 256 + cg * 64 + c);
    }
    __syncthreads();

    int tx = tid & 15, ty = tid >> 4;
    float acc[8][4];
#pragma unroll
    for (int i = 0; i < 8; i++)
#pragma unroll
        for (int j = 0; j < 4; j++) acc[i][j] = 0.f;

#pragma unroll 8
    for (int k = 0; k < 64; k++) {
        float4 wv = *(float4*)(ws + k * 64 + tx * 4);
#pragma unroll
        for (int i = 0; i < 8; i++) {
            float hv = hs[(ty * 8 + i) * 64 + k];
            acc[i][0] += hv * wv.x;
            acc[i][1] += hv * wv.y;
            acc[i][2] += hv * wv.z;
            acc[i][3] += hv * wv.w;
        }
    }
    float4 bb = *(const float4*)(B + cg * 64 + tx * 4);
#pragma unroll
    for (int i = 0; i < 8; i++) {
        int gr = r0 + ty * 8 + i;
        if (gr < N) {
            float4 o = make_float4(acc[i][0] + bb.x, acc[i][1] + bb.y,
                                   acc[i][2] + bb.z, acc[i][3] + bb.w);
            *(float4*)(out + gr * 256 + cg * 64 + tx * 4) = o;
        }
    }
}

// ---------------- edge pass 1: logits + segment-max ----------------
// one warp per edge (grid-stride); lane layout: head = lane/8, 8 d-values per lane
__global__ __launch_bounds__(256) void edge_logits(
    const int* __restrict__ src, const int* __restrict__ dst,
    const float* __restrict__ attn, int E)
{
    int gt = blockIdx.x * blockDim.x + threadIdx.x;
    int warp = gt >> 5;
    int lane = threadIdx.x & 31;
    int head = lane >> 3, dp = lane & 7;
    int off = head * 64 + dp * 8;
    float4 a0 = *(const float4*)(attn + off);
    float4 a1 = *(const float4*)(attn + off + 4);
    int nw = (gridDim.x * blockDim.x) >> 5;
    for (int e = warp; e < E; e += nw) {
        int s = src[e], dn = dst[e];
        const float* fsp = g_fs + s * 256 + off;
        const float* fdp = g_fd + dn * 256 + off;
        float4 x0 = *(const float4*)fsp;
        float4 x1 = *(const float4*)(fsp + 4);
        float4 y0 = *(const float4*)fdp;
        float4 y1 = *(const float4*)(fdp + 4);
        float p = a0.x * lrelu(x0.x + y0.x) + a0.y * lrelu(x0.y + y0.y)
                + a0.z * lrelu(x0.z + y0.z) + a0.w * lrelu(x0.w + y0.w)
                + a1.x * lrelu(x1.x + y1.x) + a1.y * lrelu(x1.y + y1.y)
                + a1.z * lrelu(x1.z + y1.z) + a1.w * lrelu(x1.w + y1.w);
        p += __shfl_down_sync(0xffffffffu, p, 4);
        p += __shfl_down_sync(0xffffffffu, p, 2);
        p += __shfl_down_sync(0xffffffffu, p, 1);
        if (dp == 0) {
            g_logit[e * 4 + head] = p;
            atomicMax(&g_menc[dn * 4 + head], fenc(p));
        }
    }
}

// ---------------- edge pass 2: ex + unnormalized scatter ----------------
__global__ __launch_bounds__(256) void edge_accum(
    const int* __restrict__ src, const int* __restrict__ dst, int E)
{
    int gt = blockIdx.x * blockDim.x + threadIdx.x;
    int warp = gt >> 5;
    int lane = threadIdx.x & 31;
    int head = lane >> 3, dp = lane & 7;
    int off = head * 64 + dp * 8;
    int nw = (gridDim.x * blockDim.x) >> 5;
    for (int e = warp; e < E; e += nw) {
        int s = src[e], dn = dst[e];
        float logit = g_logit[e * 4 + head];
        float m = fdec(g_menc[dn * 4 + head]);
        float ex = expf(logit - m);
        if (dp == 0) atomicAdd(&g_den[dn * 4 + head], ex);
        const float* fsp = g_fs + s * 256 + off;
        float4 x0 = *(const float4*)fsp;
        float4 x1 = *(const float4*)(fsp + 4);
        float* op = g_acc + dn * 256 + off;
        red2(op,     ex * x0.x, ex * x0.y);
        red2(op + 2, ex * x0.z, ex * x0.w);
        red2(op + 4, ex * x1.x, ex * x1.y);
        red2(op + 6, ex * x1.z, ex * x1.w);
    }
}

// ---------------- node finalize: normalize, relu, head-mean, BN stats ----------------
__global__ void node_finalize(int N) {
    int d = threadIdx.x;         // 0..63
    int ty = threadIdx.y;        // 0..3
    int n0 = blockIdx.x * 64;
    float sum = 0.f, sq = 0.f;
    for (int j = ty; j < 64; j += 4) {
        int n = n0 + j;
        if (n >= N) break;
        float v = 0.f;
#pragma unroll
        for (int h = 0; h < 4; h++) {
            float den = g_den[n * 4 + h];
            float o = g_acc[n * 256 + h * 64 + d];
            if (den > 0.f) v += fmaxf(o / den, 0.f);
        }
        v *= 0.25f;
        g_h[n * 64 + d] = v;
        sum += v; sq += v * v;
    }
    __shared__ float ss[4][64], s2[4][64];
    ss[ty][d] = sum; s2[ty][d] = sq;
    __syncthreads();
    if (ty == 0) {
        float s = ss[0][d] + ss[1][d] + ss[2][d] + ss[3][d];
        float q = s2[0][d] + s2[1][d] + s2[2][d] + s2[3][d];
        atomicAdd(&g_bnsum[d], s);
        atomicAdd(&g_bnsq[d], q);
    }
}

// ---------------- apply BN + graph sum-pool ----------------
__global__ void bn_pool(int N, const float* __restrict__ g, const float* __restrict__ b,
                        const int* __restrict__ gid)
{
    int idx = blockIdx.x * blockDim.x + threadIdx.x;
    int stride = gridDim.x * blockDim.x;
    float invN = 1.f / (float)N;
    for (int i = idx; i < N * 64; i += stride) {
        int d = i & 63;
        int n = i >> 6;
        float mu = g_bnsum[d] * invN;
        float var = g_bnsq[d] * invN - mu * mu;
        float v = (g_h[i] - mu) * rsqrtf(var + 1e-5f) * g[d] + b[d];
        g_h[i] = v;
        atomicAdd(&g_pooled[gid[n] * 64 + d], v);
    }
}

// ---------------- per-layer pooled MLP + BN -> g_cat ----------------
__global__ __launch_bounds__(256) void pool_mlp(
    int li, const float* __restrict__ W, const float* __restrict__ B,
    const float* __restrict__ g, const float* __restrict__ bt)
{
    __shared__ float R[128 * 64];
    __shared__ float mu1[64], iv1[64];
    int t = threadIdx.x;
    int c = t & 63, rb = t >> 6;
    for (int j = 0; j < 32; j++) {
        int r = rb + j * 4;
        float acc = B[c];
        for (int k = 0; k < 64; k++) acc += g_pooled[r * 64 + k] * W[k * 64 + c];
        R[r * 64 + c] = fmaxf(acc, 0.f);
    }
    __syncthreads();
    if (t < 64) {
        float s = 0.f, q = 0.f;
        for (int r = 0; r < 128; r++) { float v = R[r * 64 + t]; s += v; q += v * v; }
        float mu = s * (1.f / 128.f);
        float var = q * (1.f / 128.f) - mu * mu;
        mu1[t] = mu; iv1[t] = rsqrtf(var + 1e-5f);
    }
    __syncthreads();
    for (int j = 0; j < 32; j++) {
        int r = rb + j * 4;
        g_cat[r * 192 + li * 64 + c] = (R[r * 64 + c] - mu1[c]) * iv1[c] * g[c] + bt[c];
    }
}

// ---------------- final head: cat@blW -> BN -> @llW -> BN -> log_softmax ----------------
__global__ __launch_bounds__(256) void final_kernel(
    const float* __restrict__ blW, const float* __restrict__ blb,
    const float* __restrict__ blg, const float* __restrict__ blbt,
    const float* __restrict__ llW, const float* __restrict__ llb,
    const float* __restrict__ llg, const float* __restrict__ llbt,
    float* __restrict__ out, int write_hh)
{
    __shared__ float S1[128 * 64];
    __shared__ float S2[128 * 10];
    __shared__ float mu1[64], iv1[64];
    __shared__ float mu2[10], iv2[10];
    int t = threadIdx.x;
    int c = t & 63, rb = t >> 6;

    // phase A: cat[128,192] @ blW[192,64] + b, relu
    for (int j = 0; j < 32; j++) {
        int r = rb + j * 4;
        float acc = blb[c];
        for (int k = 0; k < 192; k++) acc += g_cat[r * 192 + k] * blW[k * 64 + c];
        S1[r * 64 + c] = fmaxf(acc, 0.f);
    }
    __syncthreads();

    // phase B: BN over 128 rows -> pooled_hh
    if (t < 64) {
        float s = 0.f, q = 0.f;
        for (int r = 0; r < 128; r++) { float v = S1[r * 64 + t]; s += v; q += v * v; }
        float mu = s * (1.f / 128.f);
        float var = q * (1.f / 128.f) - mu * mu;
        mu1[t] = mu; iv1[t] = rsqrtf(var + 1e-5f);
    }
    __syncthreads();
    for (int j = 0; j < 32; j++) {
        int r = rb + j * 4;
        float v = (S1[r * 64 + c] - mu1[c]) * iv1[c] * blg[c] + blbt[c];
        S1[r * 64 + c] = v;
        if (write_hh) out[1280 + r * 64 + c] = v;
    }
    __syncthreads();

    // phase C: pooled_hh @ llW[64,10] + b, relu
    if (t < 128) {
        int r = t;
        for (int cc = 0; cc < 10; cc++) {
            float acc = llb[cc];
            for (int k = 0; k < 64; k++) acc += S1[r * 64 + k] * llW[k * 10 + cc];
            S2[r * 10 + cc] = fmaxf(acc, 0.f);
        }
    }
    __syncthreads();
    if (t < 10) {
        float s = 0.f, q = 0.f;
        for (int r = 0; r < 128; r++) { float v = S2[r * 10 + t]; s += v; q += v * v; }
        float mu = s * (1.f / 128.f);
        float var = q * (1.f / 128.f) - mu * mu;
        mu2[t] = mu; iv2[t] = rsqrtf(var + 1e-5f);
    }
    __syncthreads();
    if (t < 128) {
        int r = t;
        float x[10];
        float m = -1e30f;
        for (int cc = 0; cc < 10; cc++) {
            x[cc] = (S2[r * 10 + cc] - mu2[cc]) * iv2[cc] * llg[cc] + llbt[cc];
            m = fmaxf(m, x[cc]);
        }
        float se = 0.f;
        for (int cc = 0; cc < 10; cc++) se += expf(x[cc] - m);
        float lse = m + logf(se);
        for (int cc = 0; cc < 10; cc++) out[r * 10 + cc] = x[cc] - lse;
    }
}

// ---------------- host launcher ----------------
extern "C" void kernel_launch(void* const* d_in, const int* in_sizes, int n_in,
                              void* d_out, int out_size)
{
    const float* feat = (const float*)d_in[0];
    const float* Wsrc = (const float*)d_in[1];
    const float* bsrc = (const float*)d_in[2];
    const float* Wdst = (const float*)d_in[3];
    const float* bdst = (const float*)d_in[4];
    const float* attn = (const float*)d_in[5];
    const float* bng  = (const float*)d_in[6];
    const float* bnb  = (const float*)d_in[7];
    const float* lpW  = (const float*)d_in[8];
    const float* lpb  = (const float*)d_in[9];
    const float* lpg  = (const float*)d_in[10];
    const float* lpbt = (const float*)d_in[11];
    const float* blW  = (const float*)d_in[12];
    const float* blb  = (const float*)d_in[13];
    const float* blg  = (const float*)d_in[14];
    const float* blbt = (const float*)d_in[15];
    const float* llW  = (const float*)d_in[16];
    const float* llb  = (const float*)d_in[17];
    const float* llg  = (const float*)d_in[18];
    const float* llbt = (const float*)d_in[19];
    const int* src = (const int*)d_in[20];
    const int* dst = (const int*)d_in[21];
    const int* gid = (const int*)d_in[22];

    int N = in_sizes[0] / 64;
    int E = in_sizes[20];
    float* out = (float*)d_out;

    for (int i = 0; i < 3; i++) {
        init_layer<<<512, 256>>>(N);
        gemm_kernel<<<dim3((N + 127) / 128, 4, 2), 256>>>(
            feat, i == 0 ? 1 : 0, N,
            Wsrc + i * 64 * 256, bsrc + i * 256,
            Wdst + i * 64 * 256, bdst + i * 256);
        edge_logits<<<2048, 256>>>(src, dst, attn + i * 256, E);
        edge_accum<<<2048, 256>>>(src, dst, E);
        node_finalize<<<(N + 63) / 64, dim3(64, 4)>>>(N);
        bn_pool<<<1024, 256>>>(N, bng + i * 64, bnb + i * 64, gid);
        pool_mlp<<<1, 256>>>(i, lpW + i * 64 * 64, lpb + i * 64, lpg + i * 64, lpbt + i * 64);
    }
    final_kernel<<<1, 256>>>(blW, blb, blg, blbt, llW, llb, llg, llbt,
                             out, out_size >= 128 * 74 ? 1 : 0);
}

// round 3
// speedup vs baseline: 2.5505x; 2.5505x over previous
#include <cuda_runtime.h>
#include <cuda_bf16.h>

#define MAXN 50048
#define MAXE 800256
#define NG 128

// ---------------- device scratch (static, no allocation) ----------------
__device__ float g_fs[MAXN * 256];
__device__ float g_fd[MAXN * 256];
__device__ float g_h[MAXN * 64];
__device__ int   g_cnt[MAXN];
__device__ int   g_rowptr[MAXN + 1];
__device__ int   g_cursor[MAXN];
__device__ int   g_csrsrc[MAXE];
__device__ float g_bnsum[64];
__device__ float g_bnsq[64];
__device__ float g_pooled[NG * 64];
__device__ float g_cat[NG * 192];

__device__ __forceinline__ float lrelu(float x) { return x > 0.f ? x : 0.2f * x; }

// ================= CSR build (once per launch) =================
__global__ void hist_zero(int N) {
    int i = blockIdx.x * blockDim.x + threadIdx.x;
    if (i < N) g_cnt[i] = 0;
}
__global__ void hist_kernel(const int* __restrict__ dst, int E) {
    int i = blockIdx.x * blockDim.x + threadIdx.x;
    int stride = gridDim.x * blockDim.x;
    for (int e = i; e < E; e += stride) atomicAdd(&g_cnt[dst[e]], 1);
}
__global__ __launch_bounds__(1024) void scan_kernel(int N, int E) {
    __shared__ int warpsum[32];
    int t = threadIdx.x;
    int chunk = (N + 1023) >> 10;
    int b = t * chunk, e = min(b + chunk, N);
    int s = 0;
    for (int i = b; i < e; i++) s += g_cnt[i];
    int lane = t & 31, wid = t >> 5;
    int v = s;
#pragma unroll
    for (int o = 1; o < 32; o <<= 1) {
        int u = __shfl_up_sync(0xffffffffu, v, o);
        if (lane >= o) v += u;
    }
    if (lane == 31) warpsum[wid] = v;
    __syncthreads();
    if (wid == 0) {
        int w = warpsum[lane];
#pragma unroll
        for (int o = 1; o < 32; o <<= 1) {
            int u = __shfl_up_sync(0xffffffffu, w, o);
            if (lane >= o) w += u;
        }
        warpsum[lane] = w;
    }
    __syncthreads();
    int offset = (wid > 0 ? warpsum[wid - 1] : 0) + (v - s);  // exclusive prefix
    int run = offset;
    for (int i = b; i < e; i++) {
        g_rowptr[i] = run;
        g_cursor[i] = run;
        run += g_cnt[i];
    }
    if (t == 1023) g_rowptr[N] = E;
}
__global__ void scatter_kernel(const int* __restrict__ src, const int* __restrict__ dst, int E) {
    int i = blockIdx.x * blockDim.x + threadIdx.x;
    int stride = gridDim.x * blockDim.x;
    for (int e = i; e < E; e += stride) {
        int p = atomicAdd(&g_cursor[dst[e]], 1);
        g_csrsrc[p] = src[e];
    }
}

// ================= per-layer small init =================
__global__ void zero_small() {
    int i = blockIdx.x * blockDim.x + threadIdx.x;
    if (i < NG * 64) g_pooled[i] = 0.f;
    if (i < 64) { g_bnsum[i] = 0.f; g_bnsq[i] = 0.f; }
}

// ================= node GEMM: fs/fd = h @ W + b =================
__global__ __launch_bounds__(256) void gemm_kernel(
    const float* __restrict__ feat, int use_feat, int N,
    const float* __restrict__ Ws, const float* __restrict__ bs,
    const float* __restrict__ Wd, const float* __restrict__ bd)
{
    __shared__ float hs[128 * 64];
    __shared__ float ws[64 * 64];
    const float* H = use_feat ? feat : g_h;
    const float* W; const float* B; float* out;
    if (blockIdx.z == 0) { W = Ws; B = bs; out = g_fs; }
    else                 { W = Wd; B = bd; out = g_fd; }
    int cg = blockIdx.y;
    int r0 = blockIdx.x * 128;
    int tid = threadIdx.x;

    for (int idx = tid * 4; idx < 128 * 64; idx += 1024) {
        int r = idx >> 6;
        int gr = r0 + r;
        float4 v = make_float4(0.f, 0.f, 0.f, 0.f);
        if (gr < N) v = *(const float4*)(H + gr * 64 + (idx & 63));
        *(float4*)(hs + idx) = v;
    }
    for (int idx = tid * 4; idx < 64 * 64; idx += 1024) {
        int k = idx >> 6, c = idx & 63;
        *(float4*)(ws + idx) = *(const float4*)(W + k * 256 + cg * 64 + c);
    }
    __syncthreads();

    int tx = tid & 15, ty = tid >> 4;
    float acc[8][4];
#pragma unroll
    for (int i = 0; i < 8; i++)
#pragma unroll
        for (int j = 0; j < 4; j++) acc[i][j] = 0.f;

#pragma unroll
    for (int k = 0; k < 64; k += 4) {
        float4 w0 = *(float4*)(ws + (k + 0) * 64 + tx * 4);
        float4 w1 = *(float4*)(ws + (k + 1) * 64 + tx * 4);
        float4 w2 = *(float4*)(ws + (k + 2) * 64 + tx * 4);
        float4 w3 = *(float4*)(ws + (k + 3) * 64 + tx * 4);
#pragma unroll
        for (int i = 0; i < 8; i++) {
            float4 hv = *(float4*)(hs + (ty * 8 + i) * 64 + k);
            acc[i][0] += hv.x * w0.x + hv.y * w1.x + hv.z * w2.x + hv.w * w3.x;
            acc[i][1] += hv.x * w0.y + hv.y * w1.y + hv.z * w2.y + hv.w * w3.y;
            acc[i][2] += hv.x * w0.z + hv.y * w1.z + hv.z * w2.z + hv.w * w3.z;
            acc[i][3] += hv.x * w0.w + hv.y * w1.w + hv.z * w2.w + hv.w * w3.w;
        }
    }
    float4 bb = *(const float4*)(B + cg * 64 + tx * 4);
#pragma unroll
    for (int i = 0; i < 8; i++) {
        int gr = r0 + ty * 8 + i;
        if (gr < N) {
            float4 o = make_float4(acc[i][0] + bb.x, acc[i][1] + bb.y,
                                   acc[i][2] + bb.z, acc[i][3] + bb.w);
            *(float4*)(out + gr * 256 + cg * 64 + tx * 4) = o;
        }
    }
}

// ================= fused edge aggregation: online softmax per dst node =================
// one warp per node; lane = head*8 + dp, each lane owns 8 dims of one head
__global__ __launch_bounds__(256) void agg_kernel(const float* __restrict__ attn, int N)
{
    __shared__ float bsum[64], bsq[64];
    int t = threadIdx.x;
    if (t < 64) { bsum[t] = 0.f; bsq[t] = 0.f; }
    __syncthreads();

    int lane = t & 31;
    int head = lane >> 3, dp = lane & 7;
    int off = head * 64 + dp * 8;
    int n = blockIdx.x * 8 + (t >> 5);

    if (n < N) {
        float4 a0 = *(const float4*)(attn + off);
        float4 a1 = *(const float4*)(attn + off + 4);
        const float* fdp_ = g_fd + (size_t)n * 256 + off;
        float4 y0 = *(const float4*)fdp_;
        float4 y1 = *(const float4*)(fdp_ + 4);

        int beg = g_rowptr[n], end = g_rowptr[n + 1];
        float m = -3.0e38f, den = 0.f;
        float ac[8];
#pragma unroll
        for (int j = 0; j < 8; j++) ac[j] = 0.f;

        int s = (beg < end) ? g_csrsrc[beg] : 0;
        for (int i = beg; i < end; i++) {
            int s_next = (i + 1 < end) ? g_csrsrc[i + 1] : 0;
            const float* fsp = g_fs + (size_t)s * 256 + off;
            float4 x0 = *(const float4*)fsp;
            float4 x1 = *(const float4*)(fsp + 4);
            float p = a0.x * lrelu(x0.x + y0.x) + a0.y * lrelu(x0.y + y0.y)
                    + a0.z * lrelu(x0.z + y0.z) + a0.w * lrelu(x0.w + y0.w)
                    + a1.x * lrelu(x1.x + y1.x) + a1.y * lrelu(x1.y + y1.y)
                    + a1.z * lrelu(x1.z + y1.z) + a1.w * lrelu(x1.w + y1.w);
            p += __shfl_xor_sync(0xffffffffu, p, 1);
            p += __shfl_xor_sync(0xffffffffu, p, 2);
            p += __shfl_xor_sync(0xffffffffu, p, 4);
            float mn = fmaxf(m, p);
            float sc = __expf(m - mn);
            float w  = __expf(p - mn);
            den = den * sc + w;
            ac[0] = ac[0] * sc + w * x0.x;
            ac[1] = ac[1] * sc + w * x0.y;
            ac[2] = ac[2] * sc + w * x0.z;
            ac[3] = ac[3] * sc + w * x0.w;
            ac[4] = ac[4] * sc + w * x1.x;
            ac[5] = ac[5] * sc + w * x1.y;
            ac[6] = ac[6] * sc + w * x1.z;
            ac[7] = ac[7] * sc + w * x1.w;
            m = mn;
            s = s_next;
        }
        float inv = (end > beg) ? (0.25f / den) : 0.f;
        float v[8];
#pragma unroll
        for (int j = 0; j < 8; j++) v[j] = fmaxf(ac[j], 0.f) * inv;
        // sum across 4 heads (lanes differing in bits 3,4)
#pragma unroll
        for (int j = 0; j < 8; j++) {
            v[j] += __shfl_xor_sync(0xffffffffu, v[j], 8);
            v[j] += __shfl_xor_sync(0xffffffffu, v[j], 16);
        }
        if (head == 0) {
            float4 o0 = make_float4(v[0], v[1], v[2], v[3]);
            float4 o1 = make_float4(v[4], v[5], v[6], v[7]);
            *(float4*)(g_h + (size_t)n * 64 + dp * 8)     = o0;
            *(float4*)(g_h + (size_t)n * 64 + dp * 8 + 4) = o1;
#pragma unroll
            for (int j = 0; j < 8; j++) {
                atomicAdd(&bsum[dp * 8 + j], v[j]);
                atomicAdd(&bsq[dp * 8 + j], v[j] * v[j]);
            }
        }
    }
    __syncthreads();
    if (t < 64) {
        atomicAdd(&g_bnsum[t], bsum[t]);
        atomicAdd(&g_bnsq[t], bsq[t]);
    }
}

// ================= apply BN + graph sum-pool =================
__global__ void bn_pool(int N, const float* __restrict__ g, const float* __restrict__ b,
                        const int* __restrict__ gid)
{
    int idx = blockIdx.x * blockDim.x + threadIdx.x;
    int stride = gridDim.x * blockDim.x;
    float invN = 1.f / (float)N;
    for (int i = idx; i < N * 64; i += stride) {
        int d = i & 63;
        int n = i >> 6;
        float mu = g_bnsum[d] * invN;
        float var = g_bnsq[d] * invN - mu * mu;
        float v = (g_h[i] - mu) * rsqrtf(var + 1e-5f) * g[d] + b[d];
        g_h[i] = v;
        atomicAdd(&g_pooled[gid[n] * 64 + d], v);
    }
}

// ================= per-layer pooled MLP + BN -> g_cat =================
__global__ __launch_bounds__(256) void pool_mlp(
    int li, const float* __restrict__ W, const float* __restrict__ B,
    const float* __restrict__ g, const float* __restrict__ bt)
{
    __shared__ float R[128 * 64];
    __shared__ float mu1[64], iv1[64];
    int t = threadIdx.x;
    int c = t & 63, rb = t >> 6;
    for (int j = 0; j < 32; j++) {
        int r = rb + j * 4;
        float acc = B[c];
        for (int k = 0; k < 64; k++) acc += g_pooled[r * 64 + k] * W[k * 64 + c];
        R[r * 64 + c] = fmaxf(acc, 0.f);
    }
    __syncthreads();
    if (t < 64) {
        float s = 0.f, q = 0.f;
        for (int r = 0; r < 128; r++) { float v = R[r * 64 + t]; s += v; q += v * v; }
        float mu = s * (1.f / 128.f);
        float var = q * (1.f / 128.f) - mu * mu;
        mu1[t] = mu; iv1[t] = rsqrtf(var + 1e-5f);
    }
    __syncthreads();
    for (int j = 0; j < 32; j++) {
        int r = rb + j * 4;
        g_cat[r * 192 + li * 64 + c] = (R[r * 64 + c] - mu1[c]) * iv1[c] * g[c] + bt[c];
    }
}

// ================= final head =================
__global__ __launch_bounds__(256) void final_kernel(
    const float* __restrict__ blW, const float* __restrict__ blb,
    const float* __restrict__ blg, const float* __restrict__ blbt,
    const float* __restrict__ llW, const float* __restrict__ llb,
    const float* __restrict__ llg, const float* __restrict__ llbt,
    float* __restrict__ out, int write_hh)
{
    __shared__ float S1[128 * 64];
    __shared__ float S2[128 * 10];
    __shared__ float mu1[64], iv1[64];
    __shared__ float mu2[10], iv2[10];
    int t = threadIdx.x;
    int c = t & 63, rb = t >> 6;

    for (int j = 0; j < 32; j++) {
        int r = rb + j * 4;
        float acc = blb[c];
        for (int k = 0; k < 192; k++) acc += g_cat[r * 192 + k] * blW[k * 64 + c];
        S1[r * 64 + c] = fmaxf(acc, 0.f);
    }
    __syncthreads();

    if (t < 64) {
        float s = 0.f, q = 0.f;
        for (int r = 0; r < 128; r++) { float v = S1[r * 64 + t]; s += v; q += v * v; }
        float mu = s * (1.f / 128.f);
        float var = q * (1.f / 128.f) - mu * mu;
        mu1[t] = mu; iv1[t] = rsqrtf(var + 1e-5f);
    }
    __syncthreads();
    for (int j = 0; j < 32; j++) {
        int r = rb + j * 4;
        float v = (S1[r * 64 + c] - mu1[c]) * iv1[c] * blg[c] + blbt[c];
        S1[r * 64 + c] = v;
        if (write_hh) out[1280 + r * 64 + c] = v;
    }
    __syncthreads();

    if (t < 128) {
        int r = t;
        for (int cc = 0; cc < 10; cc++) {
            float acc = llb[cc];
            for (int k = 0; k < 64; k++) acc += S1[r * 64 + k] * llW[k * 10 + cc];
            S2[r * 10 + cc] = fmaxf(acc, 0.f);
        }
    }
    __syncthreads();
    if (t < 10) {
        float s = 0.f, q = 0.f;
        for (int r = 0; r < 128; r++) { float v = S2[r * 10 + t]; s += v; q += v * v; }
        float mu = s * (1.f / 128.f);
        float var = q * (1.f / 128.f) - mu * mu;
        mu2[t] = mu; iv2[t] = rsqrtf(var + 1e-5f);
    }
    __syncthreads();
    if (t < 128) {
        int r = t;
        float x[10];
        float m = -1e30f;
        for (int cc = 0; cc < 10; cc++) {
            x[cc] = (S2[r * 10 + cc] - mu2[cc]) * iv2[cc] * llg[cc] + llbt[cc];
            m = fmaxf(m, x[cc]);
        }
        float se = 0.f;
        for (int cc = 0; cc < 10; cc++) se += expf(x[cc] - m);
        float lse = m + logf(se);
        for (int cc = 0; cc < 10; cc++) out[r * 10 + cc] = x[cc] - lse;
    }
}

// ================= host launcher =================
extern "C" void kernel_launch(void* const* d_in, const int* in_sizes, int n_in,
                              void* d_out, int out_size)
{
    const float* feat = (const float*)d_in[0];
    const float* Wsrc = (const float*)d_in[1];
    const float* bsrc = (const float*)d_in[2];
    const float* Wdst = (const float*)d_in[3];
    const float* bdst = (const float*)d_in[4];
    const float* attn = (const float*)d_in[5];
    const float* bng  = (const float*)d_in[6];
    const float* bnb  = (const float*)d_in[7];
    const float* lpW  = (const float*)d_in[8];
    const float* lpb  = (const float*)d_in[9];
    const float* lpg  = (const float*)d_in[10];
    const float* lpbt = (const float*)d_in[11];
    const float* blW  = (const float*)d_in[12];
    const float* blb  = (const float*)d_in[13];
    const float* blg  = (const float*)d_in[14];
    const float* blbt = (const float*)d_in[15];
    const float* llW  = (const float*)d_in[16];
    const float* llb  = (const float*)d_in[17];
    const float* llg  = (const float*)d_in[18];
    const float* llbt = (const float*)d_in[19];
    const int* src = (const int*)d_in[20];
    const int* dst = (const int*)d_in[21];
    const int* gid = (const int*)d_in[22];

    int N = in_sizes[0] / 64;
    int E = in_sizes[20];
    float* out = (float*)d_out;

    // build CSR (dst-sorted) once
    hist_zero<<<(N + 255) / 256, 256>>>(N);
    hist_kernel<<<1024, 256>>>(dst, E);
    scan_kernel<<<1, 1024>>>(N, E);
    scatter_kernel<<<1024, 256>>>(src, dst, E);

    for (int i = 0; i < 3; i++) {
        zero_small<<<32, 256>>>();
        gemm_kernel<<<dim3((N + 127) / 128, 4, 2), 256>>>(
            feat, i == 0 ? 1 : 0, N,
            Wsrc + i * 64 * 256, bsrc + i * 256,
            Wdst + i * 64 * 256, bdst + i * 256);
        agg_kernel<<<(N + 7) / 8, 256>>>(attn + i * 256, N);
        bn_pool<<<1024, 256>>>(N, bng + i * 64, bnb + i * 64, gid);
        pool_mlp<<<1, 256>>>(i, lpW + i * 64 * 64, lpb + i * 64, lpg + i * 64, lpbt + i * 64);
    }
    final_kernel<<<1, 256>>>(blW, blb, blg, blbt, llW, llb, llg, llbt,
                             out, out_size >= 128 * 74 ? 1 : 0);
}

// round 4
// speedup vs baseline: 2.9257x; 1.1471x over previous
#include <cuda_runtime.h>
#include <cuda_bf16.h>

#define MAXN 50048
#define MAXE 800256
#define NG 128

typedef unsigned long long u64;

// ---------------- device scratch ----------------
__device__ float g_fs[MAXN * 256];
__device__ float g_fd[MAXN * 256];
__device__ float g_h[MAXN * 64];
__device__ int   g_cnt[MAXN];
__device__ int   g_rowptr[MAXN + 1];
__device__ int   g_cursor[MAXN];
__device__ int   g_csrsrc[MAXE];
__device__ float g_bnsum[64];
__device__ float g_bnsq[64];
__device__ float g_pooled[NG * 64];
__device__ float g_cat[NG * 192];

__device__ __forceinline__ float lrelu(float x) { return x > 0.f ? x : 0.2f * x; }

__device__ __forceinline__ u64 dup2(float v) {
    u64 r; asm("mov.b64 %0, {%1, %1};" : "=l"(r) : "f"(v)); return r;
}
__device__ __forceinline__ void fma2(u64& d, u64 a, u64 b) {
    asm("fma.rn.f32x2 %0, %1, %2, %0;" : "+l"(d) : "l"(a), "l"(b));
}
__device__ __forceinline__ float2 unpk(u64 v) {
    float2 f; asm("mov.b64 {%0, %1}, %2;" : "=f"(f.x), "=f"(f.y) : "l"(v)); return f;
}

// ================= CSR build (once per launch) =================
__global__ void hist_zero(int N) {
    int i = blockIdx.x * blockDim.x + threadIdx.x;
    if (i < N) g_cnt[i] = 0;
}
__global__ void hist_kernel(const int* __restrict__ dst, int E) {
    int i = blockIdx.x * blockDim.x + threadIdx.x;
    int stride = gridDim.x * blockDim.x;
    for (int e = i; e < E; e += stride) atomicAdd(&g_cnt[dst[e]], 1);
}
__global__ __launch_bounds__(1024) void scan_kernel(int N, int E) {
    __shared__ int warpsum[32];
    int t = threadIdx.x;
    int chunk = (N + 1023) >> 10;
    int b = t * chunk, e = min(b + chunk, N);
    int s = 0;
    for (int i = b; i < e; i++) s += g_cnt[i];
    int lane = t & 31, wid = t >> 5;
    int v = s;
#pragma unroll
    for (int o = 1; o < 32; o <<= 1) {
        int u = __shfl_up_sync(0xffffffffu, v, o);
        if (lane >= o) v += u;
    }
    if (lane == 31) warpsum[wid] = v;
    __syncthreads();
    if (wid == 0) {
        int w = warpsum[lane];
#pragma unroll
        for (int o = 1; o < 32; o <<= 1) {
            int u = __shfl_up_sync(0xffffffffu, w, o);
            if (lane >= o) w += u;
        }
        warpsum[lane] = w;
    }
    __syncthreads();
    int offset = (wid > 0 ? warpsum[wid - 1] : 0) + (v - s);
    int run = offset;
    for (int i = b; i < e; i++) {
        g_rowptr[i] = run;
        g_cursor[i] = run;
        run += g_cnt[i];
    }
    if (t == 1023) g_rowptr[N] = E;
}
__global__ void scatter_kernel(const int* __restrict__ src, const int* __restrict__ dst, int E) {
    int i = blockIdx.x * blockDim.x + threadIdx.x;
    int stride = gridDim.x * blockDim.x;
    for (int e = i; e < E; e += stride) {
        int p = atomicAdd(&g_cursor[dst[e]], 1);
        g_csrsrc[p] = src[e];
    }
}

// ================= per-layer small init =================
__global__ void zero_small() {
    int i = blockIdx.x * blockDim.x + threadIdx.x;
    if (i < NG * 64) g_pooled[i] = 0.f;
    if (i < 64) { g_bnsum[i] = 0.f; g_bnsq[i] = 0.f; }
}

// ================= node GEMM with packed f32x2 FFMA =================
// tile 128 rows x 128 cols; 256 threads; 8x8 micro-tile per thread (row pairs packed)
// grid: (ceil(N/128), 2 col-halves, 2 matrices); dynamic smem
#define HS_PITCH 130
__global__ __launch_bounds__(256, 2) void gemm_kernel(
    const float* __restrict__ feat, int use_feat, int N,
    const float* __restrict__ Ws, const float* __restrict__ bs,
    const float* __restrict__ Wd, const float* __restrict__ bd)
{
    extern __shared__ float smem[];
    float* hs = smem;                    // [64][130] transposed: hs[k][row]
    float* ws = smem + 64 * HS_PITCH;    // [64][128]

    const float* H = use_feat ? feat : g_h;
    const float* W; const float* B; float* out;
    if (blockIdx.z == 0) { W = Ws; B = bs; out = g_fs; }
    else                 { W = Wd; B = bd; out = g_fd; }
    int col0 = blockIdx.y * 128;
    int r0 = blockIdx.x * 128;
    int tid = threadIdx.x;

    // load H tile (128 rows x 64 k), transposed into hs[k][row]
#pragma unroll
    for (int it = 0; it < 8; it++) {
        int idx = tid + it * 256;            // 0..2047
        int r = idx >> 4;
        int k = (idx & 15) << 2;
        float4 v = make_float4(0.f, 0.f, 0.f, 0.f);
        if (r0 + r < N) v = *(const float4*)(H + (size_t)(r0 + r) * 64 + k);
        hs[(k + 0) * HS_PITCH + r] = v.x;
        hs[(k + 1) * HS_PITCH + r] = v.y;
        hs[(k + 2) * HS_PITCH + r] = v.z;
        hs[(k + 3) * HS_PITCH + r] = v.w;
    }
    // load W tile 64 x 128
#pragma unroll
    for (int it = 0; it < 8; it++) {
        int idx = (tid + it * 256) * 4;      // 0..8191 step 4 over 64*128
        int k = idx >> 7;
        int c = idx & 127;
        *(float4*)(ws + k * 128 + c) = *(const float4*)(W + k * 256 + col0 + c);
    }
    __syncthreads();

    int tx = tid & 15, ty = tid >> 4;     // tx: 16 col groups of 8, ty: 16 row groups of 8
    u64 acc[4][8];
#pragma unroll
    for (int rp = 0; rp < 4; rp++)
#pragma unroll
        for (int c = 0; c < 8; c++) acc[rp][c] = 0ULL;

    const float* hbase = hs + ty * 8;
    const float* wbase = ws + tx * 8;
#pragma unroll 8
    for (int k = 0; k < 64; k++) {
        u64 a0 = *(const u64*)(hbase + k * HS_PITCH + 0);
        u64 a1 = *(const u64*)(hbase + k * HS_PITCH + 2);
        u64 a2 = *(const u64*)(hbase + k * HS_PITCH + 4);
        u64 a3 = *(const u64*)(hbase + k * HS_PITCH + 6);
        float4 w0 = *(const float4*)(wbase + k * 128);
        float4 w1 = *(const float4*)(wbase + k * 128 + 4);
        float wv[8] = {w0.x, w0.y, w0.z, w0.w, w1.x, w1.y, w1.z, w1.w};
#pragma unroll
        for (int c = 0; c < 8; c++) {
            u64 bcol = dup2(wv[c]);
            fma2(acc[0][c], a0, bcol);
            fma2(acc[1][c], a1, bcol);
            fma2(acc[2][c], a2, bcol);
            fma2(acc[3][c], a3, bcol);
        }
    }

    float4 bb0 = *(const float4*)(B + col0 + tx * 8);
    float4 bb1 = *(const float4*)(B + col0 + tx * 8 + 4);
    float bias[8] = {bb0.x, bb0.y, bb0.z, bb0.w, bb1.x, bb1.y, bb1.z, bb1.w};
#pragma unroll
    for (int rp = 0; rp < 4; rp++) {
        int grA = r0 + ty * 8 + rp * 2;
        int grB = grA + 1;
        float oa[8], ob[8];
#pragma unroll
        for (int c = 0; c < 8; c++) {
            float2 f = unpk(acc[rp][c]);
            oa[c] = f.x + bias[c];
            ob[c] = f.y + bias[c];
        }
        if (grA < N) {
            float* p = out + (size_t)grA * 256 + col0 + tx * 8;
            *(float4*)p = make_float4(oa[0], oa[1], oa[2], oa[3]);
            *(float4*)(p + 4) = make_float4(oa[4], oa[5], oa[6], oa[7]);
        }
        if (grB < N) {
            float* p = out + (size_t)grB * 256 + col0 + tx * 8;
            *(float4*)p = make_float4(ob[0], ob[1], ob[2], ob[3]);
            *(float4*)(p + 4) = make_float4(ob[4], ob[5], ob[6], ob[7]);
        }
    }
}

// ================= fused edge aggregation: online softmax, 2-edge unroll =================
__global__ __launch_bounds__(256) void agg_kernel(const float* __restrict__ attn, int N)
{
    __shared__ float bsum[64], bsq[64];
    int t = threadIdx.x;
    if (t < 64) { bsum[t] = 0.f; bsq[t] = 0.f; }
    __syncthreads();

    int lane = t & 31;
    int head = lane >> 3, dp = lane & 7;
    int off = head * 64 + dp * 8;
    int n = blockIdx.x * 8 + (t >> 5);

    if (n < N) {
        float4 a0 = *(const float4*)(attn + off);
        float4 a1 = *(const float4*)(attn + off + 4);
        const float* fdp_ = g_fd + (size_t)n * 256 + off;
        float4 y0 = *(const float4*)fdp_;
        float4 y1 = *(const float4*)(fdp_ + 4);

        int beg = g_rowptr[n], end = g_rowptr[n + 1];
        float m = -3.0e38f, den = 0.f;
        float ac[8];
#pragma unroll
        for (int j = 0; j < 8; j++) ac[j] = 0.f;

        int i = beg;
        for (; i + 2 <= end; i += 2) {
            int s0 = g_csrsrc[i], s1 = g_csrsrc[i + 1];
            const float* f0 = g_fs + (size_t)s0 * 256 + off;
            const float* f1 = g_fs + (size_t)s1 * 256 + off;
            float4 x00 = *(const float4*)f0;
            float4 x01 = *(const float4*)(f0 + 4);
            float4 x10 = *(const float4*)f1;
            float4 x11 = *(const float4*)(f1 + 4);
            float p0 = a0.x * lrelu(x00.x + y0.x) + a0.y * lrelu(x00.y + y0.y)
                     + a0.z * lrelu(x00.z + y0.z) + a0.w * lrelu(x00.w + y0.w)
                     + a1.x * lrelu(x01.x + y1.x) + a1.y * lrelu(x01.y + y1.y)
                     + a1.z * lrelu(x01.z + y1.z) + a1.w * lrelu(x01.w + y1.w);
            float p1 = a0.x * lrelu(x10.x + y0.x) + a0.y * lrelu(x10.y + y0.y)
                     + a0.z * lrelu(x10.z + y0.z) + a0.w * lrelu(x10.w + y0.w)
                     + a1.x * lrelu(x11.x + y1.x) + a1.y * lrelu(x11.y + y1.y)
                     + a1.z * lrelu(x11.z + y1.z) + a1.w * lrelu(x11.w + y1.w);
            p0 += __shfl_xor_sync(0xffffffffu, p0, 1);
            p1 += __shfl_xor_sync(0xffffffffu, p1, 1);
            p0 += __shfl_xor_sync(0xffffffffu, p0, 2);
            p1 += __shfl_xor_sync(0xffffffffu, p1, 2);
            p0 += __shfl_xor_sync(0xffffffffu, p0, 4);
            p1 += __shfl_xor_sync(0xffffffffu, p1, 4);
            float mn = fmaxf(m, fmaxf(p0, p1));
            float sc = __expf(m - mn);
            float w0 = __expf(p0 - mn);
            float w1 = __expf(p1 - mn);
            den = den * sc + w0 + w1;
            ac[0] = ac[0] * sc + w0 * x00.x + w1 * x10.x;
            ac[1] = ac[1] * sc + w0 * x00.y + w1 * x10.y;
            ac[2] = ac[2] * sc + w0 * x00.z + w1 * x10.z;
            ac[3] = ac[3] * sc + w0 * x00.w + w1 * x10.w;
            ac[4] = ac[4] * sc + w0 * x01.x + w1 * x11.x;
            ac[5] = ac[5] * sc + w0 * x01.y + w1 * x11.y;
            ac[6] = ac[6] * sc + w0 * x01.z + w1 * x11.z;
            ac[7] = ac[7] * sc + w0 * x01.w + w1 * x11.w;
            m = mn;
        }
        if (i < end) {
            int s0 = g_csrsrc[i];
            const float* f0 = g_fs + (size_t)s0 * 256 + off;
            float4 x00 = *(const float4*)f0;
            float4 x01 = *(const float4*)(f0 + 4);
            float p0 = a0.x * lrelu(x00.x + y0.x) + a0.y * lrelu(x00.y + y0.y)
                     + a0.z * lrelu(x00.z + y0.z) + a0.w * lrelu(x00.w + y0.w)
                     + a1.x * lrelu(x01.x + y1.x) + a1.y * lrelu(x01.y + y1.y)
                     + a1.z * lrelu(x01.z + y1.z) + a1.w * lrelu(x01.w + y1.w);
            p0 += __shfl_xor_sync(0xffffffffu, p0, 1);
            p0 += __shfl_xor_sync(0xffffffffu, p0, 2);
            p0 += __shfl_xor_sync(0xffffffffu, p0, 4);
            float mn = fmaxf(m, p0);
            float sc = __expf(m - mn);
            float w0 = __expf(p0 - mn);
            den = den * sc + w0;
            ac[0] = ac[0] * sc + w0 * x00.x;
            ac[1] = ac[1] * sc + w0 * x00.y;
            ac[2] = ac[2] * sc + w0 * x00.z;
            ac[3] = ac[3] * sc + w0 * x00.w;
            ac[4] = ac[4] * sc + w0 * x01.x;
            ac[5] = ac[5] * sc + w0 * x01.y;
            ac[6] = ac[6] * sc + w0 * x01.z;
            ac[7] = ac[7] * sc + w0 * x01.w;
        }
        float inv = (end > beg) ? (0.25f / den) : 0.f;
        float v[8];
#pragma unroll
        for (int j = 0; j < 8; j++) v[j] = fmaxf(ac[j], 0.f) * inv;
#pragma unroll
        for (int j = 0; j < 8; j++) {
            v[j] += __shfl_xor_sync(0xffffffffu, v[j], 8);
            v[j] += __shfl_xor_sync(0xffffffffu, v[j], 16);
        }
        if (head == 0) {
            *(float4*)(g_h + (size_t)n * 64 + dp * 8)     = make_float4(v[0], v[1], v[2], v[3]);
            *(float4*)(g_h + (size_t)n * 64 + dp * 8 + 4) = make_float4(v[4], v[5], v[6], v[7]);
#pragma unroll
            for (int j = 0; j < 8; j++) {
                atomicAdd(&bsum[dp * 8 + j], v[j]);
                atomicAdd(&bsq[dp * 8 + j], v[j] * v[j]);
            }
        }
    }
    __syncthreads();
    if (t < 64) {
        atomicAdd(&g_bnsum[t], bsum[t]);
        atomicAdd(&g_bnsq[t], bsq[t]);
    }
}

// ================= apply BN + graph sum-pool (smem staged; gid sorted) =================
__global__ __launch_bounds__(256) void bn_pool(int N, const float* __restrict__ g,
                                               const float* __restrict__ b,
                                               const int* __restrict__ gid)
{
    __shared__ float sp[4][64];
    __shared__ int sg0, sspan;
    int t = threadIdx.x;
    int n0 = blockIdx.x * 64;
    int nend = min(n0 + 64, N);
    if (n0 >= N) return;
    if (t == 0) { int a = gid[n0], z = gid[nend - 1]; sg0 = a; sspan = z - a + 1; }
    sp[t >> 6][t & 63] = 0.f;
    __syncthreads();

    float invN = 1.f / (float)N;
    int d = t & 63;
    float mu = g_bnsum[d] * invN;
    float var = g_bnsq[d] * invN - mu * mu;
    float scale = rsqrtf(var + 1e-5f) * g[d];
    float bias = b[d] - mu * scale;
    bool fast = (sspan <= 4);
    int g0 = sg0;
    int cnt = (nend - n0) * 64;
    for (int i = t; i < cnt; i += 256) {
        int n = n0 + (i >> 6);
        float v = g_h[(size_t)n * 64 + d] * scale + bias;
        g_h[(size_t)n * 64 + d] = v;
        if (fast) atomicAdd(&sp[gid[n] - g0][d], v);
        else      atomicAdd(&g_pooled[gid[n] * 64 + d], v);
    }
    __syncthreads();
    if (fast) {
        for (int j = t; j < sspan * 64; j += 256)
            atomicAdd(&g_pooled[(g0 + (j >> 6)) * 64 + (j & 63)], sp[j >> 6][j & 63]);
    }
}

// ================= per-layer pooled MLP + BN -> g_cat =================
__global__ __launch_bounds__(256) void pool_mlp(
    int li, const float* __restrict__ W, const float* __restrict__ B,
    const float* __restrict__ g, const float* __restrict__ bt)
{
    __shared__ float R[128 * 64];
    __shared__ float mu1[64], iv1[64];
    int t = threadIdx.x;
    int c = t & 63, rb = t >> 6;
    for (int j = 0; j < 32; j++) {
        int r = rb + j * 4;
        float acc = B[c];
        for (int k = 0; k < 64; k++) acc += g_pooled[r * 64 + k] * W[k * 64 + c];
        R[r * 64 + c] = fmaxf(acc, 0.f);
    }
    __syncthreads();
    if (t < 64) {
        float s = 0.f, q = 0.f;
        for (int r = 0; r < 128; r++) { float v = R[r * 64 + t]; s += v; q += v * v; }
        float mu = s * (1.f / 128.f);
        float var = q * (1.f / 128.f) - mu * mu;
        mu1[t] = mu; iv1[t] = rsqrtf(var + 1e-5f);
    }
    __syncthreads();
    for (int j = 0; j < 32; j++) {
        int r = rb + j * 4;
        g_cat[r * 192 + li * 64 + c] = (R[r * 64 + c] - mu1[c]) * iv1[c] * g[c] + bt[c];
    }
}

// ================= final head =================
__global__ __launch_bounds__(256) void final_kernel(
    const float* __restrict__ blW, const float* __restrict__ blb,
    const float* __restrict__ blg, const float* __restrict__ blbt,
    const float* __restrict__ llW, const float* __restrict__ llb,
    const float* __restrict__ llg, const float* __restrict__ llbt,
    float* __restrict__ out, int write_hh)
{
    __shared__ float S1[128 * 64];
    __shared__ float S2[128 * 10];
    __shared__ float mu1[64], iv1[64];
    __shared__ float mu2[10], iv2[10];
    int t = threadIdx.x;
    int c = t & 63, rb = t >> 6;

    for (int j = 0; j < 32; j++) {
        int r = rb + j * 4;
        float acc = blb[c];
        for (int k = 0; k < 192; k++) acc += g_cat[r * 192 + k] * blW[k * 64 + c];
        S1[r * 64 + c] = fmaxf(acc, 0.f);
    }
    __syncthreads();

    if (t < 64) {
        float s = 0.f, q = 0.f;
        for (int r = 0; r < 128; r++) { float v = S1[r * 64 + t]; s += v; q += v * v; }
        float mu = s * (1.f / 128.f);
        float var = q * (1.f / 128.f) - mu * mu;
        mu1[t] = mu; iv1[t] = rsqrtf(var + 1e-5f);
    }
    __syncthreads();
    for (int j = 0; j < 32; j++) {
        int r = rb + j * 4;
        float v = (S1[r * 64 + c] - mu1[c]) * iv1[c] * blg[c] + blbt[c];
        S1[r * 64 + c] = v;
        if (write_hh) out[1280 + r * 64 + c] = v;
    }
    __syncthreads();

    if (t < 128) {
        int r = t;
        for (int cc = 0; cc < 10; cc++) {
            float acc = llb[cc];
            for (int k = 0; k < 64; k++) acc += S1[r * 64 + k] * llW[k * 10 + cc];
            S2[r * 10 + cc] = fmaxf(acc, 0.f);
        }
    }
    __syncthreads();
    if (t < 10) {
        float s = 0.f, q = 0.f;
        for (int r = 0; r < 128; r++) { float v = S2[r * 10 + t]; s += v; q += v * v; }
        float mu = s * (1.f / 128.f);
        float var = q * (1.f / 128.f) - mu * mu;
        mu2[t] = mu; iv2[t] = rsqrtf(var + 1e-5f);
    }
    __syncthreads();
    if (t < 128) {
        int r = t;
        float x[10];
        float m = -1e30f;
        for (int cc = 0; cc < 10; cc++) {
            x[cc] = (S2[r * 10 + cc] - mu2[cc]) * iv2[cc] * llg[cc] + llbt[cc];
            m = fmaxf(m, x[cc]);
        }
        float se = 0.f;
        for (int cc = 0; cc < 10; cc++) se += expf(x[cc] - m);
        float lse = m + logf(se);
        for (int cc = 0; cc < 10; cc++) out[r * 10 + cc] = x[cc] - lse;
    }
}

// ================= host launcher =================
extern "C" void kernel_launch(void* const* d_in, const int* in_sizes, int n_in,
                              void* d_out, int out_size)
{
    const float* feat = (const float*)d_in[0];
    const float* Wsrc = (const float*)d_in[1];
    const float* bsrc = (const float*)d_in[2];
    const float* Wdst = (const float*)d_in[3];
    const float* bdst = (const float*)d_in[4];
    const float* attn = (const float*)d_in[5];
    const float* bng  = (const float*)d_in[6];
    const float* bnb  = (const float*)d_in[7];
    const float* lpW  = (const float*)d_in[8];
    const float* lpb  = (const float*)d_in[9];
    const float* lpg  = (const float*)d_in[10];
    const float* lpbt = (const float*)d_in[11];
    const float* blW  = (const float*)d_in[12];
    const float* blb  = (const float*)d_in[13];
    const float* blg  = (const float*)d_in[14];
    const float* blbt = (const float*)d_in[15];
    const float* llW  = (const float*)d_in[16];
    const float* llb  = (const float*)d_in[17];
    const float* llg  = (const float*)d_in[18];
    const float* llbt = (const float*)d_in[19];
    const int* src = (const int*)d_in[20];
    const int* dst = (const int*)d_in[21];
    const int* gid = (const int*)d_in[22];

    int N = in_sizes[0] / 64;
    int E = in_sizes[20];
    float* out = (float*)d_out;

    const int GEMM_SMEM = (64 * HS_PITCH + 64 * 128) * 4;   // 66,048 B
    cudaFuncSetAttribute(gemm_kernel, cudaFuncAttributeMaxDynamicSharedMemorySize, GEMM_SMEM);

    // build CSR (dst-sorted) once
    hist_zero<<<(N + 255) / 256, 256>>>(N);
    hist_kernel<<<1024, 256>>>(dst, E);
    scan_kernel<<<1, 1024>>>(N, E);
    scatter_kernel<<<1024, 256>>>(src, dst, E);

    for (int i = 0; i < 3; i++) {
        zero_small<<<32, 256>>>();
        gemm_kernel<<<dim3((N + 127) / 128, 2, 2), 256, GEMM_SMEM>>>(
            feat, i == 0 ? 1 : 0, N,
            Wsrc + i * 64 * 256, bsrc + i * 256,
            Wdst + i * 64 * 256, bdst + i * 256);
        agg_kernel<<<(N + 7) / 8, 256>>>(attn + i * 256, N);
        bn_pool<<<(N + 63) / 64, 256>>>(N, bng + i * 64, bnb + i * 64, gid);
        pool_mlp<<<1, 256>>>(i, lpW + i * 64 * 64, lpb + i * 64, lpg + i * 64, lpbt + i * 64);
    }
    final_kernel<<<1, 256>>>(blW, blb, blg, blbt, llW, llb, llg, llbt,
                             out, out_size >= 128 * 74 ? 1 : 0);
}